// round 8
// baseline (speedup 1.0000x reference)
#include <cuda_runtime.h>
#include <cuda_fp16.h>
#include <cstdint>
#include <cstddef>

// ---------------- problem dims ----------------
#define B_ 2048
#define O_ 512
#define H_ 1024
#define P_ 1024
#define C_ 512
#define T_ 12
#define BH (B_*H_)
#define BP (B_*P_)
#define BC (B_*C_)

#define NTHREADS 256

// ---------- f16-acc GEMM tiles (U + steps) ----------
#define TM 128
#define TN 128
#define TKC 64
#define STAGES 2
#define ABYTES (TM*TKC*2)          // 16KB
#define BBYTES (TKC*TN*2)          // 16KB
#define BUFBYTES (ABYTES+BBYTES)   // 32KB
#define SMEM16 (STAGES*BUFBYTES)   // 64KB

// ---------- fp32-acc OH GEMM tiles (round-7 proven) ----------
#define OTN 64
#define OABYTES (TM*TKC*2)
#define OBUFBYTES ((TM+TKC)*TKC*2) // 24576
#define SMEM32 (3*OBUFBYTES)

#define MODE_U    1
#define MODE_STEP 2

// ---------------- device scratch ----------------
__device__ __align__(16) __half g_in16[B_*O_];
__device__ __align__(16) __half g_AH16[(size_t)T_*BH];
__device__ __align__(16) __half g_U16[(size_t)T_*BP];        // fp16 now
__device__ float  g_p[BP];
__device__ float  g_c[BC];
__device__ __align__(16) __half g_ap16A[BP];
__device__ __align__(16) __half g_ap16B[BP];
__device__ __align__(16) __half g_ac16A[BC];
__device__ __align__(16) __half g_ac16B[BC];
__device__ __align__(16) __half g_w16_oh[O_*H_];
__device__ __align__(16) __half g_w16_hp[H_*P_];
__device__ __align__(16) __half g_w16_pp[P_*P_];
__device__ __align__(16) __half g_w16_pc[P_*C_];
__device__ __align__(16) __half g_w16_cp[C_*P_];
__device__ float g_csp_pp0[8*P_];
__device__ float g_csp_cp[8*P_];
__device__ float g_csp_pc[8*C_];

__device__ const float c_sc[T_] = {
    0.0f, 0.25f, 0.4375f, 0.578125f, 0.68359375f, 0.7626953125f,
    0.822021484375f, 0.86651611328125f, 0.8998870849609375f,
    0.92491531372070312f, 0.94368648529052734f, 0.95776486396789551f};

// ---------------- helpers ----------------
__device__ __forceinline__ uint32_t smem_u32(const void* p) {
    uint32_t a;
    asm("{ .reg .u64 t; cvta.to.shared.u64 t, %1; cvt.u32.u64 %0, t; }" : "=r"(a) : "l"(p));
    return a;
}
__device__ __forceinline__ void cpasync16(uint32_t dst, const void* src) {
    asm volatile("cp.async.cg.shared.global [%0], [%1], 16;" :: "r"(dst), "l"(src));
}
__device__ __forceinline__ void ldsm_x4(uint32_t* r, uint32_t addr) {
    asm volatile("ldmatrix.sync.aligned.m8n8.x4.shared.b16 {%0,%1,%2,%3}, [%4];"
        : "=r"(r[0]), "=r"(r[1]), "=r"(r[2]), "=r"(r[3]) : "r"(addr));
}
__device__ __forceinline__ void ldsm_x4t(uint32_t* r, uint32_t addr) {
    asm volatile("ldmatrix.sync.aligned.m8n8.x4.trans.shared.b16 {%0,%1,%2,%3}, [%4];"
        : "=r"(r[0]), "=r"(r[1]), "=r"(r[2]), "=r"(r[3]) : "r"(addr));
}
__device__ __forceinline__ void mma_f16f32(float* c, const uint32_t* a, const uint32_t* b) {
    asm volatile(
        "mma.sync.aligned.m16n8k16.row.col.f32.f16.f16.f32 "
        "{%0,%1,%2,%3},{%4,%5,%6,%7},{%8,%9},{%0,%1,%2,%3};"
        : "+f"(c[0]), "+f"(c[1]), "+f"(c[2]), "+f"(c[3])
        : "r"(a[0]), "r"(a[1]), "r"(a[2]), "r"(a[3]), "r"(b[0]), "r"(b[1]));
}
__device__ __forceinline__ void mma_f16h(uint32_t* c, const uint32_t* a, const uint32_t* b) {
    asm volatile(
        "mma.sync.aligned.m16n8k16.row.col.f16.f16.f16.f16 "
        "{%0,%1},{%2,%3,%4,%5},{%6,%7},{%0,%1};"
        : "+r"(c[0]), "+r"(c[1])
        : "r"(a[0]), "r"(a[1]), "r"(a[2]), "r"(a[3]), "r"(b[0]), "r"(b[1]));
}
__device__ __forceinline__ float sigmoidf_(float x) { return 1.0f / (1.0f + __expf(-x)); }

// A tile swizzle: rows of 64 halves (8 x 16B groups)
__device__ __forceinline__ uint32_t swzA(int row, int q) {
    return (uint32_t)((row << 6) + (((q ^ row) & 7) << 3));
}
// B tile swizzle: rows of 128 halves (16 x 16B groups)
__device__ __forceinline__ uint32_t swzB(int row, int q) {
    return (uint32_t)((row << 7) + ((((q & 8) | ((q ^ row) & 7))) << 3));
}

// =================== f16-acc GEMM (U + steps), warp tile 32x64 ===================
__global__ void __launch_bounds__(NTHREADS, 3) k_gemm16(
    int mode, int t,
    const float* __restrict__ bias_p,
    const float* __restrict__ bias_c,
    float* __restrict__ out)
{
    extern __shared__ __half smem[];
    const int tid = threadIdx.x, lane = tid & 31, wid = tid >> 5;
    const int wm = wid >> 1, wn = wid & 1;       // 4(m) x 2(n); warp tile 32x64
    const int l7 = lane & 7;

    const __half *a0 = nullptr, *b0 = nullptr, *a1 = nullptr, *b1 = nullptr;
    int lda0 = 0, ldb0 = 0, lda1 = 0, ldb1 = 0, ch0 = 0, ch1 = 0;
    int m0 = blockIdx.x * TM;
    int n0 = 0;
    int epi = 1;  // 1=U store, 2=P step, 3=C step
    const __half* ap_in  = (t & 1) ? g_ap16A : g_ap16B;
    __half*       ap_out = (t & 1) ? g_ap16B : g_ap16A;
    const __half* ac_in  = (t & 1) ? g_ac16A : g_ac16B;
    __half*       ac_out = (t & 1) ? g_ac16B : g_ac16A;

    if (mode == MODE_U) {
        n0 = blockIdx.y * TN;
        a0 = g_AH16 + (size_t)m0 * H_; lda0 = H_; ch0 = H_/TKC;        // 16
        b0 = g_w16_hp + n0; ldb0 = P_;
        epi = 1;
    } else {
        if (blockIdx.y < 8) {
            n0 = blockIdx.y * TN;
            a0 = ap_in + (size_t)m0 * P_; lda0 = P_; ch0 = P_/TKC;     // 16
            b0 = g_w16_pp + n0; ldb0 = P_;
            a1 = ac_in + (size_t)m0 * C_; lda1 = C_; ch1 = C_/TKC;     // 8
            b1 = g_w16_cp + n0; ldb1 = P_;
            epi = 2;
        } else {
            n0 = (blockIdx.y - 8) * TN;
            a0 = ap_in + (size_t)m0 * P_; lda0 = P_; ch0 = P_/TKC;
            b0 = g_w16_pc + n0; ldb0 = C_;
            epi = 3;
        }
    }
    const int NC = ch0 + ch1;
    const uint32_t sbase = smem_u32(smem);

    auto issue_chunk = [&](int c, int buf) {
        const __half *ga, *gb; int la, lb;
        if (c < ch0) { ga = a0 + (size_t)c*TKC;        gb = b0 + (size_t)c*TKC*ldb0;        la = lda0; lb = ldb0; }
        else         { ga = a1 + (size_t)(c-ch0)*TKC;  gb = b1 + (size_t)(c-ch0)*TKC*ldb1;  la = lda1; lb = ldb1; }
        uint32_t sA = sbase + buf*BUFBYTES;
        uint32_t sB = sA + ABYTES;
#pragma unroll
        for (int it = 0; it < 4; ++it) {          // A: 1024 16B vectors (128 rows x 8)
            int v = tid + it * NTHREADS;
            int row = v >> 3, q = v & 7;
            cpasync16(sA + swzA(row, q)*2, ga + (size_t)row*la + q*8);
        }
#pragma unroll
        for (int it = 0; it < 4; ++it) {          // B: 1024 16B vectors (64 rows x 16)
            int v = tid + it * NTHREADS;
            int row = v >> 4, q = v & 15;
            cpasync16(sB + swzB(row, q)*2, gb + (size_t)row*lb + q*8);
        }
        asm volatile("cp.async.commit_group;");
    };

    uint32_t acc[2][8][2];
#pragma unroll
    for (int mi = 0; mi < 2; mi++)
#pragma unroll
        for (int ni = 0; ni < 8; ni++) { acc[mi][ni][0] = 0u; acc[mi][ni][1] = 0u; }

    const int a_rbase = wm*32 + l7 + ((lane >> 3) & 1) * 8;
    const int a_cgoff = (lane >> 4);
    const int b_krow_l = (lane & 15);
    const int b_cg0 = wn*8 + (lane >> 4);

    issue_chunk(0, 0);
    issue_chunk(1, 1);

    for (int c = 0; c < NC; ++c) {
        if (c + 1 < NC) { asm volatile("cp.async.wait_group 1;" ::: "memory"); }
        else            { asm volatile("cp.async.wait_group 0;" ::: "memory"); }
        __syncthreads();
        uint32_t sA = sbase + (c & 1)*BUFBYTES;
        uint32_t sB = sA + ABYTES;
#pragma unroll
        for (int ks = 0; ks < 4; ++ks) {
            uint32_t af[2][4], bf[4][4];
            {
                int cg = ks*2 + a_cgoff;
#pragma unroll
                for (int mi = 0; mi < 2; mi++)
                    ldsm_x4(af[mi], sA + swzA(a_rbase + mi*16, cg)*2);
            }
            {
                int krow = ks*16 + b_krow_l;
#pragma unroll
                for (int j = 0; j < 4; j++)
                    ldsm_x4t(bf[j], sB + swzB(krow, b_cg0 + j*2)*2);
            }
#pragma unroll
            for (int mi = 0; mi < 2; mi++)
#pragma unroll
                for (int ni = 0; ni < 8; ni++)
                    mma_f16h(acc[mi][ni], af[mi], bf[ni >> 1] + (ni & 1)*2);
        }
        __syncthreads();
        if (c + 2 < NC) issue_chunk(c + 2, c & 1);
    }

    // ---------------- fused epilogue ----------------
    auto epilog2 = [&](int m, int n, float v0, float v1) {
        if (epi == 1) {
            float2 bp = *(const float2*)(bias_p + n);
            *(__half2*)(g_U16 + (size_t)m*P_ + n) = __floats2half2_rn(v0 + bp.x, v1 + bp.y);
        } else if (epi == 2) {
            size_t idx = (size_t)m*P_ + n;
            float2 u  = __half22float2(*(const __half2*)(g_U16 + (size_t)t*BP + idx));
            float2 po = *(const float2*)(g_p + idx);
            float2 pn, s;
            pn.x = 0.25f*(v0 + u.x) + 0.75f*po.x; s.x = sigmoidf_(pn.x);
            pn.y = 0.25f*(v1 + u.y) + 0.75f*po.y; s.y = sigmoidf_(pn.y);
            *(float2*)(g_p + idx) = pn;
            *(float2*)(out + (size_t)t*BP + idx) = s;
            *(__half2*)(ap_out + idx) = __floats2half2_rn(s.x, s.y);
        } else {
            size_t idx = (size_t)m*C_ + n;
            float2 bc = *(const float2*)(bias_c + n);
            float2 co = *(const float2*)(g_c + idx);
            float2 cn, s;
            cn.x = 0.25f*(v0 + bc.x) + 0.75f*co.x; s.x = sigmoidf_(cn.x);
            cn.y = 0.25f*(v1 + bc.y) + 0.75f*co.y; s.y = sigmoidf_(cn.y);
            *(float2*)(g_c + idx) = cn;
            *(__half2*)(ac_out + idx) = __floats2half2_rn(s.x, s.y);
        }
    };

#pragma unroll
    for (int mi = 0; mi < 2; mi++) {
#pragma unroll
        for (int ni = 0; ni < 8; ni++) {
            int m = m0 + wm*32 + mi*16 + (lane >> 2);
            int n = n0 + wn*64 + ni*8 + 2*(lane & 3);
            float2 lo = __half22float2(*(__half2*)&acc[mi][ni][0]);
            float2 hi = __half22float2(*(__half2*)&acc[mi][ni][1]);
            epilog2(m,     n, lo.x, lo.y);
            epilog2(m + 8, n, hi.x, hi.y);
        }
    }
}

// =================== fp32-acc OH GEMM (round-7 proven; epi OH only) ===================
__global__ void __launch_bounds__(NTHREADS, 3) k_gemm_oh(
    const float* __restrict__ bias_h)
{
    extern __shared__ __half smem[];
    const int tid = threadIdx.x, lane = tid & 31, wid = tid >> 5;
    const int wm = wid >> 1, wn = wid & 1;       // 4(m) x 2(n); warp tile 32x32
    const int l7 = lane & 7;

    int m0 = blockIdx.x * TM;
    int n0 = blockIdx.y * OTN;
    const __half* a0 = g_in16 + (size_t)m0 * O_; const int lda0 = O_;
    const __half* b0 = g_w16_oh + n0;            const int ldb0 = H_;
    const int NC = O_/TKC;                       // 8
    const uint32_t sbase = smem_u32(smem);

    auto issue_chunk = [&](int c, int buf) {
        const __half* ga = a0 + (size_t)c*TKC;
        const __half* gb = b0 + (size_t)c*TKC*ldb0;
        uint32_t sA = sbase + buf*OBUFBYTES;
        uint32_t sB = sA + OABYTES;
#pragma unroll
        for (int it = 0; it < 4; ++it) {
            int v = tid + it * NTHREADS;
            int row = v >> 3, q = v & 7;
            cpasync16(sA + swzA(row, q)*2, ga + (size_t)row*lda0 + q*8);
        }
#pragma unroll
        for (int it = 0; it < 2; ++it) {
            int v = tid + it * NTHREADS;
            int row = v >> 3, q = v & 7;
            cpasync16(sB + swzA(row, q)*2, gb + (size_t)row*ldb0 + q*8);
        }
        asm volatile("cp.async.commit_group;");
    };

    float acc[2][4][4];
#pragma unroll
    for (int mi = 0; mi < 2; mi++)
#pragma unroll
        for (int ni = 0; ni < 4; ni++)
#pragma unroll
            for (int q = 0; q < 4; q++) acc[mi][ni][q] = 0.0f;

    const int a_rbase = wm*32 + l7 + ((lane >> 3) & 1) * 8;
    const int a_cgoff = (lane >> 4);
    const int b_krow_l = (lane & 15);
    const int b_cg0 = wn*4 + (lane >> 4);

    issue_chunk(0, 0);
    issue_chunk(1, 1);

    for (int c = 0; c < NC; ++c) {
        if (c + 1 < NC) { asm volatile("cp.async.wait_group 1;" ::: "memory"); }
        else            { asm volatile("cp.async.wait_group 0;" ::: "memory"); }
        __syncthreads();
        uint32_t sA = sbase + (c % 3)*OBUFBYTES;
        uint32_t sB = sA + OABYTES;
#pragma unroll
        for (int ks = 0; ks < 4; ++ks) {
            uint32_t af[2][4], bf[2][4];
            {
                int cg = ks*2 + a_cgoff;
#pragma unroll
                for (int mi = 0; mi < 2; mi++)
                    ldsm_x4(af[mi], sA + swzA(a_rbase + mi*16, cg)*2);
            }
            {
                int krow = ks*16 + b_krow_l;
#pragma unroll
                for (int j = 0; j < 2; j++)
                    ldsm_x4t(bf[j], sB + swzA(krow, b_cg0 + j*2)*2);
            }
#pragma unroll
            for (int mi = 0; mi < 2; mi++)
#pragma unroll
                for (int ni = 0; ni < 4; ni++)
                    mma_f16f32(acc[mi][ni], af[mi], bf[ni >> 1] + (ni & 1)*2);
        }
        if (c + 2 < NC) issue_chunk(c + 2, (c + 2) % 3);
    }

#pragma unroll
    for (int mi = 0; mi < 2; mi++) {
#pragma unroll
        for (int ni = 0; ni < 4; ni++) {
            int m = m0 + wm*32 + mi*16 + (lane >> 2);
            int n = n0 + wn*32 + ni*8 + 2*(lane & 3);
#pragma unroll
            for (int half = 0; half < 2; half++) {
                int mm = m + half*8;
                float v0 = acc[mi][ni][2*half], v1 = acc[mi][ni][2*half+1];
                float2 bh = *(const float2*)(bias_h + n);
                float p0 = v0 + bh.x, p1 = v1 + bh.y;
                size_t idx = (size_t)mm*H_ + n;
#pragma unroll
                for (int tt = 0; tt < T_; tt++) {
                    float sc = c_sc[tt];
                    *(__half2*)(g_AH16 + (size_t)tt*BH + idx) =
                        __floats2half2_rn(sigmoidf_(p0*sc), sigmoidf_(p1*sc));
                }
            }
        }
    }
}

// ---------------- prep: coalesced fp16 convert ----------------
__global__ void k_conv(const float* __restrict__ inputs,
                       const float* __restrict__ w_oh, const float* __restrict__ w_hp,
                       const float* __restrict__ w_pp, const float* __restrict__ w_pc,
                       const float* __restrict__ w_cp) {
    int i4 = blockIdx.x * blockDim.x + threadIdx.x;
    const int S0 = B_*O_, S1 = S0 + O_*H_, S2 = S1 + H_*P_, S3 = S2 + P_*P_,
              S4 = S3 + P_*C_, S5 = S4 + C_*P_;
    int j = i4 * 4;
    if (j >= S5) return;
    const float* src; __half* dst; int rel; bool diag = false;
    if (j < S0)      { src = inputs; dst = g_in16;  rel = j; }
    else if (j < S1) { src = w_oh;   dst = g_w16_oh; rel = j - S0; }
    else if (j < S2) { src = w_hp;   dst = g_w16_hp; rel = j - S1; }
    else if (j < S3) { src = w_pp;   dst = g_w16_pp; rel = j - S2; diag = true; }
    else if (j < S4) { src = w_pc;   dst = g_w16_pc; rel = j - S3; }
    else             { src = w_cp;   dst = g_w16_cp; rel = j - S4; }
    float4 v = *(const float4*)(src + rel);
    if (diag) {
        int k = rel >> 10, nb = rel & 1023;
        if (k == nb)     v.x = 0.0f;
        if (k == nb + 1) v.y = 0.0f;
        if (k == nb + 2) v.z = 0.0f;
        if (k == nb + 3) v.w = 0.0f;
    }
    __half2 h01 = __floats2half2_rn(v.x, v.y);
    __half2 h23 = __floats2half2_rn(v.z, v.w);
    uint2 o;
    o.x = *(uint32_t*)&h01;
    o.y = *(uint32_t*)&h23;
    *(uint2*)(dst + rel) = o;
}

// ---------------- column-sum partials ----------------
__global__ void k_colsum(const float* __restrict__ w_pp, const float* __restrict__ w_cp,
                         const float* __restrict__ w_pc) {
    int n = blockIdx.x * 256 + threadIdx.x;
    int seg = blockIdx.y;
    int mat = blockIdx.z;
    if (mat == 0) {
        int k0 = seg * 128;
        float s = 0.0f;
        for (int k = k0; k < k0 + 128; k++)
            if (k != n) s += w_pp[(size_t)k*P_ + n];
        g_csp_pp0[seg*P_ + n] = s;
    } else if (mat == 1) {
        int k0 = seg * 64;
        float s = 0.0f;
        for (int k = k0; k < k0 + 64; k++)
            s += w_cp[(size_t)k*P_ + n];
        g_csp_cp[seg*P_ + n] = s;
    } else {
        if (n >= C_) return;
        int k0 = seg * 128;
        float s = 0.0f;
        for (int k = k0; k < k0 + 128; k++)
            s += w_pc[(size_t)k*C_ + n];
        g_csp_pc[seg*C_ + n] = s;
    }
}

// ---------------- step 0 ----------------
__global__ void k_step0(const float* __restrict__ bias_c, float* __restrict__ out) {
    int i = blockIdx.x * blockDim.x + threadIdx.x;
    if (i < BP) {
        int n = i & (P_ - 1);
        float cs = 0.0f;
#pragma unroll
        for (int s = 0; s < 8; s++) cs += g_csp_pp0[s*P_ + n] + g_csp_cp[s*P_ + n];
        float pn = 0.25f * (__half2float(g_U16[i]) + 0.5f * cs);
        g_p[i] = pn;
        float sg = sigmoidf_(pn);
        out[i] = sg;
        g_ap16A[i] = __float2half(sg);
    } else if (i < BP + BC) {
        int j = i - BP;
        int n = j & (C_ - 1);
        float cs = 0.0f;
#pragma unroll
        for (int s = 0; s < 8; s++) cs += g_csp_pc[s*C_ + n];
        float cn = 0.25f * (0.5f * cs + bias_c[n]);
        g_c[j] = cn;
        g_ac16A[j] = __float2half(sigmoidf_(cn));
    }
}

// ---------------- entry point ----------------
extern "C" void kernel_launch(void* const* d_in, const int* in_sizes, int n_in,
                              void* d_out, int out_size) {
    const float* inputs = (const float*)d_in[0];
    const float* w_oh   = (const float*)d_in[1];
    const float* w_hp   = (const float*)d_in[2];
    const float* w_pp   = (const float*)d_in[3];
    const float* w_pc   = (const float*)d_in[4];
    const float* w_cp   = (const float*)d_in[5];
    const float* bias_h = (const float*)d_in[6];
    const float* bias_p = (const float*)d_in[7];
    const float* bias_c = (const float*)d_in[8];
    float* out = (float*)d_out;

    cudaFuncSetAttribute(k_gemm16, cudaFuncAttributeMaxDynamicSharedMemorySize, SMEM16);
    cudaFuncSetAttribute(k_gemm_oh, cudaFuncAttributeMaxDynamicSharedMemorySize, SMEM32);

    const int TOT4 = (B_*O_ + O_*H_ + H_*P_ + P_*P_ + P_*C_ + C_*P_) / 4;
    k_conv<<<(TOT4 + 255)/256, 256>>>(inputs, w_oh, w_hp, w_pp, w_pc, w_cp);
    k_colsum<<<dim3(4, 8, 3), 256>>>(w_pp, w_cp, w_pc);

    // OH GEMM (fp32 acc): writes g_AH16 for all 12 timesteps
    k_gemm_oh<<<dim3(B_/TM, H_/OTN), NTHREADS, SMEM32>>>(bias_h);

    // U[t] = ah_t @ w_hp + bias_p  (f16 acc, one big M=24576 GEMM)
    k_gemm16<<<dim3(T_*B_/TM, P_/TN), NTHREADS, SMEM16>>>(MODE_U, 0, bias_p, bias_c, out);

    // step 0: elementwise with column sums
    k_step0<<<(BP + BC + 255)/256, 256>>>(bias_c, out);

    // steps 1..11: p-update (8 N-tiles) + c-update (4 N-tiles)
    for (int t = 1; t < T_; t++) {
        int ny = (t == T_ - 1) ? 8 : 12;
        k_gemm16<<<dim3(B_/TM, ny), NTHREADS, SMEM16>>>(MODE_STEP, t, bias_p, bias_c, out);
    }
}

// round 9
// speedup vs baseline: 1.1090x; 1.1090x over previous
#include <cuda_runtime.h>
#include <cuda_fp16.h>
#include <cstdint>
#include <cstddef>

// ---------------- problem dims ----------------
#define B_ 2048
#define O_ 512
#define H_ 1024
#define P_ 1024
#define C_ 512
#define T_ 12
#define BH (B_*H_)
#define BP (B_*P_)
#define BC (B_*C_)

#define NTHREADS 256
#define TM 128
#define TKC 64
#define ABYTES (TM*TKC*2)          // 16KB

// OH (fp32-acc) tiles
#define OTN 64
#define OBUFBYTES ((TM+TKC)*TKC*2) // 24576
#define SMEM32 (3*OBUFBYTES)

#define MODE_U    1
#define MODE_STEP 2

// ---------------- device scratch ----------------
__device__ __align__(16) __half g_in16[B_*O_];
__device__ __align__(16) __half g_AH16[(size_t)T_*BH];
__device__ __align__(16) __half g_U16[(size_t)T_*BP];
__device__ float  g_p[BP];
__device__ float  g_c[BC];
__device__ __align__(16) __half g_ap16A[BP];
__device__ __align__(16) __half g_ap16B[BP];
__device__ __align__(16) __half g_ac16A[BC];
__device__ __align__(16) __half g_ac16B[BC];
__device__ __align__(16) __half g_w16_oh[O_*H_];
__device__ __align__(16) __half g_w16_hp[H_*P_];
__device__ __align__(16) __half g_w16_pp[P_*P_];
__device__ __align__(16) __half g_w16_pc[P_*C_];
__device__ __align__(16) __half g_w16_cp[C_*P_];
__device__ float g_csp_pp0[8*P_];
__device__ float g_csp_cp[8*P_];
__device__ float g_csp_pc[8*C_];

__device__ const float c_sc[T_] = {
    0.0f, 0.25f, 0.4375f, 0.578125f, 0.68359375f, 0.7626953125f,
    0.822021484375f, 0.86651611328125f, 0.8998870849609375f,
    0.92491531372070312f, 0.94368648529052734f, 0.95776486396789551f};

// ---------------- helpers ----------------
__device__ __forceinline__ uint32_t smem_u32(const void* p) {
    uint32_t a;
    asm("{ .reg .u64 t; cvta.to.shared.u64 t, %1; cvt.u32.u64 %0, t; }" : "=r"(a) : "l"(p));
    return a;
}
__device__ __forceinline__ void cpasync16(uint32_t dst, const void* src) {
    asm volatile("cp.async.cg.shared.global [%0], [%1], 16;" :: "r"(dst), "l"(src));
}
__device__ __forceinline__ void ldsm_x4(uint32_t* r, uint32_t addr) {
    asm volatile("ldmatrix.sync.aligned.m8n8.x4.shared.b16 {%0,%1,%2,%3}, [%4];"
        : "=r"(r[0]), "=r"(r[1]), "=r"(r[2]), "=r"(r[3]) : "r"(addr));
}
__device__ __forceinline__ void ldsm_x4t(uint32_t* r, uint32_t addr) {
    asm volatile("ldmatrix.sync.aligned.m8n8.x4.trans.shared.b16 {%0,%1,%2,%3}, [%4];"
        : "=r"(r[0]), "=r"(r[1]), "=r"(r[2]), "=r"(r[3]) : "r"(addr));
}
__device__ __forceinline__ void mma_f16f32(float* c, const uint32_t* a, const uint32_t* b) {
    asm volatile(
        "mma.sync.aligned.m16n8k16.row.col.f32.f16.f16.f32 "
        "{%0,%1,%2,%3},{%4,%5,%6,%7},{%8,%9},{%0,%1,%2,%3};"
        : "+f"(c[0]), "+f"(c[1]), "+f"(c[2]), "+f"(c[3])
        : "r"(a[0]), "r"(a[1]), "r"(a[2]), "r"(a[3]), "r"(b[0]), "r"(b[1]));
}
__device__ __forceinline__ void mma_f16h(uint32_t* c, const uint32_t* a, const uint32_t* b) {
    asm volatile(
        "mma.sync.aligned.m16n8k16.row.col.f16.f16.f16.f16 "
        "{%0,%1},{%2,%3,%4,%5},{%6,%7},{%0,%1};"
        : "+r"(c[0]), "+r"(c[1])
        : "r"(a[0]), "r"(a[1]), "r"(a[2]), "r"(a[3]), "r"(b[0]), "r"(b[1]));
}
__device__ __forceinline__ float sigmoidf_(float x) { return 1.0f / (1.0f + __expf(-x)); }

// tile swizzles
__device__ __forceinline__ uint32_t swzA(int row, int q) {   // rows of 64 halves, q 0..7
    return (uint32_t)((row << 6) + (((q ^ row) & 7) << 3));
}
__device__ __forceinline__ uint32_t swzB(int row, int q) {   // rows of 128 halves, q 0..15
    return (uint32_t)((row << 7) + ((((q & 8) | ((q ^ row) & 7))) << 3));
}

// =================== f16-acc GEMM template (U: TN=128/2st, steps: TN=64/3st) ===================
template<int TNN>
__global__ void __launch_bounds__(NTHREADS, 3) k_gemm16(
    int mode, int t,
    const float* __restrict__ bias_p,
    const float* __restrict__ bias_c,
    float* __restrict__ out)
{
    constexpr int NI = TNN / 16;             // mma n-tiles per warp (4 or 8)
    constexpr int NJ = TNN / 32;             // ldsm.x4t loads per warp (2 or 4)
    constexpr int NSTG = (TNN == 64) ? 3 : 2;
    constexpr int BBYTES = TKC * TNN * 2;
    constexpr int BUFB = ABYTES + BBYTES;

    extern __shared__ __half smem[];
    const int tid = threadIdx.x, lane = tid & 31, wid = tid >> 5;
    const int wm = wid >> 1, wn = wid & 1;   // 4(m) x 2(n); warp tile 32 x TNN/2
    const int l7 = lane & 7;

    const __half *a0 = nullptr, *b0 = nullptr, *a1 = nullptr, *b1 = nullptr;
    int lda0 = 0, ldb0 = 0, lda1 = 0, ldb1 = 0, ch0 = 0, ch1 = 0;
    int m0 = blockIdx.x * TM;
    int n0 = 0;
    int epi = 1;  // 1=U store, 2=P step, 3=C step
    const __half* ap_in  = (t & 1) ? g_ap16A : g_ap16B;
    __half*       ap_out = (t & 1) ? g_ap16B : g_ap16A;
    const __half* ac_in  = (t & 1) ? g_ac16A : g_ac16B;
    __half*       ac_out = (t & 1) ? g_ac16B : g_ac16A;

    if (mode == MODE_U) {
        n0 = blockIdx.y * TNN;
        a0 = g_AH16 + (size_t)m0 * H_; lda0 = H_; ch0 = H_/TKC;        // 16
        b0 = g_w16_hp + n0; ldb0 = P_;
        epi = 1;
    } else {
        if (blockIdx.y < P_/TNN) {
            n0 = blockIdx.y * TNN;
            a0 = ap_in + (size_t)m0 * P_; lda0 = P_; ch0 = P_/TKC;     // 16
            b0 = g_w16_pp + n0; ldb0 = P_;
            a1 = ac_in + (size_t)m0 * C_; lda1 = C_; ch1 = C_/TKC;     // 8
            b1 = g_w16_cp + n0; ldb1 = P_;
            epi = 2;
        } else {
            n0 = (blockIdx.y - P_/TNN) * TNN;
            a0 = ap_in + (size_t)m0 * P_; lda0 = P_; ch0 = P_/TKC;
            b0 = g_w16_pc + n0; ldb0 = C_;
            epi = 3;
        }
    }
    const int NC = ch0 + ch1;
    const uint32_t sbase = smem_u32(smem);

    auto issue_chunk = [&](int c, int buf) {
        const __half *ga, *gb; int la, lb;
        if (c < ch0) { ga = a0 + (size_t)c*TKC;        gb = b0 + (size_t)c*TKC*ldb0;        la = lda0; lb = ldb0; }
        else         { ga = a1 + (size_t)(c-ch0)*TKC;  gb = b1 + (size_t)(c-ch0)*TKC*ldb1;  la = lda1; lb = ldb1; }
        uint32_t sA = sbase + buf*BUFB;
        uint32_t sB = sA + ABYTES;
#pragma unroll
        for (int it = 0; it < 4; ++it) {          // A: 1024 16B vectors (128 rows x 8)
            int v = tid + it * NTHREADS;
            int row = v >> 3, q = v & 7;
            cpasync16(sA + swzA(row, q)*2, ga + (size_t)row*la + q*8);
        }
        if (TNN == 64) {
#pragma unroll
            for (int it = 0; it < 2; ++it) {      // B: 512 16B vectors (64 rows x 8)
                int v = tid + it * NTHREADS;
                int row = v >> 3, q = v & 7;
                cpasync16(sB + swzA(row, q)*2, gb + (size_t)row*lb + q*8);
            }
        } else {
#pragma unroll
            for (int it = 0; it < 4; ++it) {      // B: 1024 16B vectors (64 rows x 16)
                int v = tid + it * NTHREADS;
                int row = v >> 4, q = v & 15;
                cpasync16(sB + swzB(row, q)*2, gb + (size_t)row*lb + q*8);
            }
        }
        asm volatile("cp.async.commit_group;");
    };

    uint32_t acc[2][NI][2];
#pragma unroll
    for (int mi = 0; mi < 2; mi++)
#pragma unroll
        for (int ni = 0; ni < NI; ni++) { acc[mi][ni][0] = 0u; acc[mi][ni][1] = 0u; }

    const int a_rbase = wm*32 + l7 + ((lane >> 3) & 1) * 8;
    const int a_cgoff = (lane >> 4);
    const int b_krow_l = (lane & 15);
    const int b_cg0 = wn*(NJ*2) + (lane >> 4);

    issue_chunk(0, 0);
    issue_chunk(1, 1);

    for (int c = 0; c < NC; ++c) {
        if (c + 1 < NC) { asm volatile("cp.async.wait_group 1;" ::: "memory"); }
        else            { asm volatile("cp.async.wait_group 0;" ::: "memory"); }
        __syncthreads();
        uint32_t sA = sbase + (c % NSTG)*BUFB;
        uint32_t sB = sA + ABYTES;
#pragma unroll
        for (int ks = 0; ks < 4; ++ks) {
            uint32_t af[2][4], bf[NJ][4];
            {
                int cg = ks*2 + a_cgoff;
#pragma unroll
                for (int mi = 0; mi < 2; mi++)
                    ldsm_x4(af[mi], sA + swzA(a_rbase + mi*16, cg)*2);
            }
            {
                int krow = ks*16 + b_krow_l;
#pragma unroll
                for (int j = 0; j < NJ; j++) {
                    if (TNN == 64) ldsm_x4t(bf[j], sB + swzA(krow, b_cg0 + j*2)*2);
                    else           ldsm_x4t(bf[j], sB + swzB(krow, b_cg0 + j*2)*2);
                }
            }
#pragma unroll
            for (int mi = 0; mi < 2; mi++)
#pragma unroll
                for (int ni = 0; ni < NI; ni++)
                    mma_f16h(acc[mi][ni], af[mi], bf[ni >> 1] + (ni & 1)*2);
        }
        if (NSTG == 2) {
            // double-buffer: next issue writes the buffer being read now -> barrier first
            __syncthreads();
            if (c + 2 < NC) issue_chunk(c + 2, c & 1);
        } else {
            // 3-stage: buffer (c+2)%3's readers all passed this iteration's top barrier
            if (c + 2 < NC) issue_chunk(c + 2, (c + 2) % NSTG);
        }
    }

    // ---------------- fused epilogue ----------------
    auto epilog2 = [&](int m, int n, float v0, float v1) {
        if (epi == 1) {
            float2 bp = *(const float2*)(bias_p + n);
            *(__half2*)(g_U16 + (size_t)m*P_ + n) = __floats2half2_rn(v0 + bp.x, v1 + bp.y);
        } else if (epi == 2) {
            size_t idx = (size_t)m*P_ + n;
            float2 u  = __half22float2(*(const __half2*)(g_U16 + (size_t)t*BP + idx));
            float2 po = *(const float2*)(g_p + idx);
            float2 pn, s;
            pn.x = 0.25f*(v0 + u.x) + 0.75f*po.x; s.x = sigmoidf_(pn.x);
            pn.y = 0.25f*(v1 + u.y) + 0.75f*po.y; s.y = sigmoidf_(pn.y);
            *(float2*)(g_p + idx) = pn;
            *(float2*)(out + (size_t)t*BP + idx) = s;
            *(__half2*)(ap_out + idx) = __floats2half2_rn(s.x, s.y);
        } else {
            size_t idx = (size_t)m*C_ + n;
            float2 bc = *(const float2*)(bias_c + n);
            float2 co = *(const float2*)(g_c + idx);
            float2 cn, s;
            cn.x = 0.25f*(v0 + bc.x) + 0.75f*co.x; s.x = sigmoidf_(cn.x);
            cn.y = 0.25f*(v1 + bc.y) + 0.75f*co.y; s.y = sigmoidf_(cn.y);
            *(float2*)(g_c + idx) = cn;
            *(__half2*)(ac_out + idx) = __floats2half2_rn(s.x, s.y);
        }
    };

#pragma unroll
    for (int mi = 0; mi < 2; mi++) {
#pragma unroll
        for (int ni = 0; ni < NI; ni++) {
            int m = m0 + wm*32 + mi*16 + (lane >> 2);
            int n = n0 + wn*(TNN/2) + ni*8 + 2*(lane & 3);
            float2 lo = __half22float2(*(__half2*)&acc[mi][ni][0]);
            float2 hi = __half22float2(*(__half2*)&acc[mi][ni][1]);
            epilog2(m,     n, lo.x, lo.y);
            epilog2(m + 8, n, hi.x, hi.y);
        }
    }
}

// =================== fp32-acc OH GEMM (round-7 proven) ===================
__global__ void __launch_bounds__(NTHREADS, 3) k_gemm_oh(
    const float* __restrict__ bias_h)
{
    extern __shared__ __half smem[];
    const int tid = threadIdx.x, lane = tid & 31, wid = tid >> 5;
    const int wm = wid >> 1, wn = wid & 1;
    const int l7 = lane & 7;

    int m0 = blockIdx.x * TM;
    int n0 = blockIdx.y * OTN;
    const __half* a0 = g_in16 + (size_t)m0 * O_; const int lda0 = O_;
    const __half* b0 = g_w16_oh + n0;            const int ldb0 = H_;
    const int NC = O_/TKC;                       // 8
    const uint32_t sbase = smem_u32(smem);

    auto issue_chunk = [&](int c, int buf) {
        const __half* ga = a0 + (size_t)c*TKC;
        const __half* gb = b0 + (size_t)c*TKC*ldb0;
        uint32_t sA = sbase + buf*OBUFBYTES;
        uint32_t sB = sA + ABYTES;
#pragma unroll
        for (int it = 0; it < 4; ++it) {
            int v = tid + it * NTHREADS;
            int row = v >> 3, q = v & 7;
            cpasync16(sA + swzA(row, q)*2, ga + (size_t)row*lda0 + q*8);
        }
#pragma unroll
        for (int it = 0; it < 2; ++it) {
            int v = tid + it * NTHREADS;
            int row = v >> 3, q = v & 7;
            cpasync16(sB + swzA(row, q)*2, gb + (size_t)row*ldb0 + q*8);
        }
        asm volatile("cp.async.commit_group;");
    };

    float acc[2][4][4];
#pragma unroll
    for (int mi = 0; mi < 2; mi++)
#pragma unroll
        for (int ni = 0; ni < 4; ni++)
#pragma unroll
            for (int q = 0; q < 4; q++) acc[mi][ni][q] = 0.0f;

    const int a_rbase = wm*32 + l7 + ((lane >> 3) & 1) * 8;
    const int a_cgoff = (lane >> 4);
    const int b_krow_l = (lane & 15);
    const int b_cg0 = wn*4 + (lane >> 4);

    issue_chunk(0, 0);
    issue_chunk(1, 1);

    for (int c = 0; c < NC; ++c) {
        if (c + 1 < NC) { asm volatile("cp.async.wait_group 1;" ::: "memory"); }
        else            { asm volatile("cp.async.wait_group 0;" ::: "memory"); }
        __syncthreads();
        uint32_t sA = sbase + (c % 3)*OBUFBYTES;
        uint32_t sB = sA + ABYTES;
#pragma unroll
        for (int ks = 0; ks < 4; ++ks) {
            uint32_t af[2][4], bf[2][4];
            {
                int cg = ks*2 + a_cgoff;
#pragma unroll
                for (int mi = 0; mi < 2; mi++)
                    ldsm_x4(af[mi], sA + swzA(a_rbase + mi*16, cg)*2);
            }
            {
                int krow = ks*16 + b_krow_l;
#pragma unroll
                for (int j = 0; j < 2; j++)
                    ldsm_x4t(bf[j], sB + swzA(krow, b_cg0 + j*2)*2);
            }
#pragma unroll
            for (int mi = 0; mi < 2; mi++)
#pragma unroll
                for (int ni = 0; ni < 4; ni++)
                    mma_f16f32(acc[mi][ni], af[mi], bf[ni >> 1] + (ni & 1)*2);
        }
        if (c + 2 < NC) issue_chunk(c + 2, (c + 2) % 3);
    }

#pragma unroll
    for (int mi = 0; mi < 2; mi++) {
#pragma unroll
        for (int ni = 0; ni < 4; ni++) {
            int m = m0 + wm*32 + mi*16 + (lane >> 2);
            int n = n0 + wn*32 + ni*8 + 2*(lane & 3);
#pragma unroll
            for (int half = 0; half < 2; half++) {
                int mm = m + half*8;
                float v0 = acc[mi][ni][2*half], v1 = acc[mi][ni][2*half+1];
                float2 bh = *(const float2*)(bias_h + n);
                float p0 = v0 + bh.x, p1 = v1 + bh.y;
                size_t idx = (size_t)mm*H_ + n;
#pragma unroll
                for (int tt = 0; tt < T_; tt++) {
                    float sc = c_sc[tt];
                    *(__half2*)(g_AH16 + (size_t)tt*BH + idx) =
                        __floats2half2_rn(sigmoidf_(p0*sc), sigmoidf_(p1*sc));
                }
            }
        }
    }
}

// ---------------- prep: coalesced fp16 convert ----------------
__global__ void k_conv(const float* __restrict__ inputs,
                       const float* __restrict__ w_oh, const float* __restrict__ w_hp,
                       const float* __restrict__ w_pp, const float* __restrict__ w_pc,
                       const float* __restrict__ w_cp) {
    int i4 = blockIdx.x * blockDim.x + threadIdx.x;
    const int S0 = B_*O_, S1 = S0 + O_*H_, S2 = S1 + H_*P_, S3 = S2 + P_*P_,
              S4 = S3 + P_*C_, S5 = S4 + C_*P_;
    int j = i4 * 4;
    if (j >= S5) return;
    const float* src; __half* dst; int rel; bool diag = false;
    if (j < S0)      { src = inputs; dst = g_in16;  rel = j; }
    else if (j < S1) { src = w_oh;   dst = g_w16_oh; rel = j - S0; }
    else if (j < S2) { src = w_hp;   dst = g_w16_hp; rel = j - S1; }
    else if (j < S3) { src = w_pp;   dst = g_w16_pp; rel = j - S2; diag = true; }
    else if (j < S4) { src = w_pc;   dst = g_w16_pc; rel = j - S3; }
    else             { src = w_cp;   dst = g_w16_cp; rel = j - S4; }
    float4 v = *(const float4*)(src + rel);
    if (diag) {
        int k = rel >> 10, nb = rel & 1023;
        if (k == nb)     v.x = 0.0f;
        if (k == nb + 1) v.y = 0.0f;
        if (k == nb + 2) v.z = 0.0f;
        if (k == nb + 3) v.w = 0.0f;
    }
    __half2 h01 = __floats2half2_rn(v.x, v.y);
    __half2 h23 = __floats2half2_rn(v.z, v.w);
    uint2 o;
    o.x = *(uint32_t*)&h01;
    o.y = *(uint32_t*)&h23;
    *(uint2*)(dst + rel) = o;
}

// ---------------- column-sum partials ----------------
__global__ void k_colsum(const float* __restrict__ w_pp, const float* __restrict__ w_cp,
                         const float* __restrict__ w_pc) {
    int n = blockIdx.x * 256 + threadIdx.x;
    int seg = blockIdx.y;
    int mat = blockIdx.z;
    if (mat == 0) {
        int k0 = seg * 128;
        float s = 0.0f;
        for (int k = k0; k < k0 + 128; k++)
            if (k != n) s += w_pp[(size_t)k*P_ + n];
        g_csp_pp0[seg*P_ + n] = s;
    } else if (mat == 1) {
        int k0 = seg * 64;
        float s = 0.0f;
        for (int k = k0; k < k0 + 64; k++)
            s += w_cp[(size_t)k*P_ + n];
        g_csp_cp[seg*P_ + n] = s;
    } else {
        if (n >= C_) return;
        int k0 = seg * 128;
        float s = 0.0f;
        for (int k = k0; k < k0 + 128; k++)
            s += w_pc[(size_t)k*C_ + n];
        g_csp_pc[seg*C_ + n] = s;
    }
}

// ---------------- step 0 ----------------
__global__ void k_step0(const float* __restrict__ bias_c, float* __restrict__ out) {
    int i = blockIdx.x * blockDim.x + threadIdx.x;
    if (i < BP) {
        int n = i & (P_ - 1);
        float cs = 0.0f;
#pragma unroll
        for (int s = 0; s < 8; s++) cs += g_csp_pp0[s*P_ + n] + g_csp_cp[s*P_ + n];
        float pn = 0.25f * (__half2float(g_U16[i]) + 0.5f * cs);
        g_p[i] = pn;
        float sg = sigmoidf_(pn);
        out[i] = sg;
        g_ap16A[i] = __float2half(sg);
    } else if (i < BP + BC) {
        int j = i - BP;
        int n = j & (C_ - 1);
        float cs = 0.0f;
#pragma unroll
        for (int s = 0; s < 8; s++) cs += g_csp_pc[s*C_ + n];
        float cn = 0.25f * (0.5f * cs + bias_c[n]);
        g_c[j] = cn;
        g_ac16A[j] = __float2half(sigmoidf_(cn));
    }
}

// ---------------- entry point ----------------
extern "C" void kernel_launch(void* const* d_in, const int* in_sizes, int n_in,
                              void* d_out, int out_size) {
    const float* inputs = (const float*)d_in[0];
    const float* w_oh   = (const float*)d_in[1];
    const float* w_hp   = (const float*)d_in[2];
    const float* w_pp   = (const float*)d_in[3];
    const float* w_pc   = (const float*)d_in[4];
    const float* w_cp   = (const float*)d_in[5];
    const float* bias_h = (const float*)d_in[6];
    const float* bias_p = (const float*)d_in[7];
    const float* bias_c = (const float*)d_in[8];
    float* out = (float*)d_out;

    const int SMEM_U    = 2 * (ABYTES + TKC*128*2);   // 64KB (TN=128, 2 stages)
    const int SMEM_STEP = 3 * (ABYTES + TKC*64*2);    // 72KB (TN=64, 3 stages)

    cudaFuncSetAttribute(k_gemm16<128>, cudaFuncAttributeMaxDynamicSharedMemorySize, SMEM_U);
    cudaFuncSetAttribute(k_gemm16<64>,  cudaFuncAttributeMaxDynamicSharedMemorySize, SMEM_STEP);
    cudaFuncSetAttribute(k_gemm_oh, cudaFuncAttributeMaxDynamicSharedMemorySize, SMEM32);

    const int TOT4 = (B_*O_ + O_*H_ + H_*P_ + P_*P_ + P_*C_ + C_*P_) / 4;
    k_conv<<<(TOT4 + 255)/256, 256>>>(inputs, w_oh, w_hp, w_pp, w_pc, w_cp);
    k_colsum<<<dim3(4, 8, 3), 256>>>(w_pp, w_cp, w_pc);

    // OH GEMM (fp32 acc): writes g_AH16 for all 12 timesteps
    k_gemm_oh<<<dim3(B_/TM, H_/OTN), NTHREADS, SMEM32>>>(bias_h);

    // U[t] = ah_t @ w_hp + bias_p  (f16 acc, TN=128, one big M=24576 GEMM)
    k_gemm16<128><<<dim3(T_*B_/TM, P_/128), NTHREADS, SMEM_U>>>(MODE_U, 0, bias_p, bias_c, out);

    // step 0: elementwise with column sums
    k_step0<<<(BP + BC + 255)/256, 256>>>(bias_c, out);

    // steps 1..11: TN=64 (balanced 384-CTA grid), f16 acc
    for (int t = 1; t < T_; t++) {
        int ny = (t == T_ - 1) ? (P_/64) : (P_/64 + C_/64);   // 16 or 24
        k_gemm16<64><<<dim3(B_/TM, ny), NTHREADS, SMEM_STEP>>>(MODE_STEP, t, bias_p, bias_c, out);
    }
}

// round 10
// speedup vs baseline: 1.1382x; 1.0263x over previous
#include <cuda_runtime.h>
#include <cuda_fp16.h>
#include <cstdint>
#include <cstddef>

// ---------------- problem dims ----------------
#define B_ 2048
#define O_ 512
#define H_ 1024
#define P_ 1024
#define C_ 512
#define T_ 12
#define BH (B_*H_)
#define BP (B_*P_)
#define BC (B_*C_)

#define NTHREADS 256
#define TM 128
#define TKC 64
#define ABYTES (TM*TKC*2)          // 16KB

// OH (fp32-acc) tiles
#define OTN 64
#define OBUFBYTES ((TM+TKC)*TKC*2) // 24576
#define SMEM32 (3*OBUFBYTES)

// persistent step kernel geometry
#define SBX 16
#define SBY 24
#define NCTA_STEP (SBX*SBY)        // 384 (<= 148*3 co-resident)
#define SBUFB (ABYTES + TKC*64*2)  // 24576
#define SMEM_STEP (3*SBUFB)        // 72KB

// U GEMM (TN=128, 2-stage)
#define UBUFB (ABYTES + TKC*128*2) // 32KB
#define SMEM_U (2*UBUFB)           // 64KB

// ---------------- device scratch ----------------
__device__ __align__(16) __half g_in16[B_*O_];
__device__ __align__(16) __half g_AH16[(size_t)T_*BH];
__device__ __align__(16) __half g_U16[(size_t)T_*BP];
__device__ float  g_p[BP];
__device__ float  g_c[BC];
__device__ __align__(16) __half g_ap16A[BP];
__device__ __align__(16) __half g_ap16B[BP];
__device__ __align__(16) __half g_ac16A[BC];
__device__ __align__(16) __half g_ac16B[BC];
__device__ __align__(16) __half g_w16_oh[O_*H_];
__device__ __align__(16) __half g_w16_hp[H_*P_];
__device__ __align__(16) __half g_w16_pp[P_*P_];
__device__ __align__(16) __half g_w16_pc[P_*C_];
__device__ __align__(16) __half g_w16_cp[C_*P_];
__device__ float g_csp_pp0[8*P_];
__device__ float g_csp_cp[8*P_];
__device__ float g_csp_pc[8*C_];
__device__ unsigned g_barv;                      // grid-barrier counter (reset in k_step0)

__device__ const float c_sc[T_] = {
    0.0f, 0.25f, 0.4375f, 0.578125f, 0.68359375f, 0.7626953125f,
    0.822021484375f, 0.86651611328125f, 0.8998870849609375f,
    0.92491531372070312f, 0.94368648529052734f, 0.95776486396789551f};

// ---------------- helpers ----------------
__device__ __forceinline__ uint32_t smem_u32(const void* p) {
    uint32_t a;
    asm("{ .reg .u64 t; cvta.to.shared.u64 t, %1; cvt.u32.u64 %0, t; }" : "=r"(a) : "l"(p));
    return a;
}
__device__ __forceinline__ void cpasync16(uint32_t dst, const void* src) {
    asm volatile("cp.async.cg.shared.global [%0], [%1], 16;" :: "r"(dst), "l"(src));
}
__device__ __forceinline__ void ldsm_x4(uint32_t* r, uint32_t addr) {
    asm volatile("ldmatrix.sync.aligned.m8n8.x4.shared.b16 {%0,%1,%2,%3}, [%4];"
        : "=r"(r[0]), "=r"(r[1]), "=r"(r[2]), "=r"(r[3]) : "r"(addr));
}
__device__ __forceinline__ void ldsm_x4t(uint32_t* r, uint32_t addr) {
    asm volatile("ldmatrix.sync.aligned.m8n8.x4.trans.shared.b16 {%0,%1,%2,%3}, [%4];"
        : "=r"(r[0]), "=r"(r[1]), "=r"(r[2]), "=r"(r[3]) : "r"(addr));
}
__device__ __forceinline__ void mma_f16f32(float* c, const uint32_t* a, const uint32_t* b) {
    asm volatile(
        "mma.sync.aligned.m16n8k16.row.col.f32.f16.f16.f32 "
        "{%0,%1,%2,%3},{%4,%5,%6,%7},{%8,%9},{%0,%1,%2,%3};"
        : "+f"(c[0]), "+f"(c[1]), "+f"(c[2]), "+f"(c[3])
        : "r"(a[0]), "r"(a[1]), "r"(a[2]), "r"(a[3]), "r"(b[0]), "r"(b[1]));
}
__device__ __forceinline__ void mma_f16h(uint32_t* c, const uint32_t* a, const uint32_t* b) {
    asm volatile(
        "mma.sync.aligned.m16n8k16.row.col.f16.f16.f16.f16 "
        "{%0,%1},{%2,%3,%4,%5},{%6,%7},{%0,%1};"
        : "+r"(c[0]), "+r"(c[1])
        : "r"(a[0]), "r"(a[1]), "r"(a[2]), "r"(a[3]), "r"(b[0]), "r"(b[1]));
}
__device__ __forceinline__ float sigmoidf_(float x) { return 1.0f / (1.0f + __expf(-x)); }

__device__ __forceinline__ uint32_t swzA(int row, int q) {   // rows of 64 halves, q 0..7
    return (uint32_t)((row << 6) + (((q ^ row) & 7) << 3));
}
__device__ __forceinline__ uint32_t swzB(int row, int q) {   // rows of 128 halves, q 0..15
    return (uint32_t)((row << 7) + ((((q & 8) | ((q ^ row) & 7))) << 3));
}

// =================== persistent step kernel (all 11 steps, grid barrier) ===================
__global__ void __launch_bounds__(NTHREADS, 3) k_steps(
    const float* __restrict__ bias_c,
    float* __restrict__ out)
{
    extern __shared__ __half smem[];
    const int tid = threadIdx.x, lane = tid & 31, wid = tid >> 5;
    const int wm = wid >> 1, wn = wid & 1;
    const int l7 = lane & 7;
    const int bx = blockIdx.x & 15;          // 16 m-tiles
    const int by = blockIdx.x >> 4;          // 0..15 p-update, 16..23 c-update
    const int m0 = bx * TM;
    const int epi = (by < 16) ? 2 : 3;
    const int n0 = (epi == 2) ? by*64 : (by - 16)*64;
    const uint32_t sbase = smem_u32(smem);

    const int a_rbase = wm*32 + l7 + ((lane >> 3) & 1) * 8;
    const int a_cgoff = (lane >> 4);
    const int b_krow_l = (lane & 15);
    const int b_cg0 = wn*4 + (lane >> 4);

    const int ch0 = P_/TKC;                              // 16
    const int ch1 = (epi == 2) ? C_/TKC : 0;             // 8 or 0
    const int NC  = ch0 + ch1;
    const __half* b0 = (epi == 2) ? (g_w16_pp + n0) : (g_w16_pc + n0);
    const int ldb0   = (epi == 2) ? P_ : C_;
    const __half* b1 = g_w16_cp + n0;                    // ldb1 = P_

    for (int t = 1; t < T_; ++t) {
        if (t > 1) {
            // -------- grid barrier #(t-1) (threadFenceReduction pattern) --------
            __threadfence();
            __syncthreads();
            if (tid == 0) {
                atomicAdd(&g_barv, 1u);
                unsigned target = (unsigned)((t - 1) * NCTA_STEP);
                while (*(volatile unsigned*)&g_barv < target) { }
                __threadfence();
            }
            __syncthreads();
        }
        if (epi == 3 && t == T_ - 1) continue;   // t=11 c-state never consumed

        const __half* ap_in  = (t & 1) ? g_ap16A : g_ap16B;
        __half*       ap_out = (t & 1) ? g_ap16B : g_ap16A;
        const __half* ac_in  = (t & 1) ? g_ac16A : g_ac16B;
        __half*       ac_out = (t & 1) ? g_ac16B : g_ac16A;
        const __half* a0 = ap_in + (size_t)m0 * P_;
        const __half* a1 = ac_in + (size_t)m0 * C_;

        auto issue_chunk = [&](int c, int buf) {
            const __half *ga, *gb; int la, lb;
            if (c < ch0) { ga = a0 + (size_t)c*TKC;        gb = b0 + (size_t)c*TKC*ldb0; la = P_; lb = ldb0; }
            else         { ga = a1 + (size_t)(c-ch0)*TKC;  gb = b1 + (size_t)(c-ch0)*TKC*P_; la = C_; lb = P_; }
            uint32_t sA = sbase + buf*SBUFB;
            uint32_t sB = sA + ABYTES;
#pragma unroll
            for (int it = 0; it < 4; ++it) {
                int v = tid + it * NTHREADS;
                int row = v >> 3, q = v & 7;
                cpasync16(sA + swzA(row, q)*2, ga + (size_t)row*la + q*8);
            }
#pragma unroll
            for (int it = 0; it < 2; ++it) {
                int v = tid + it * NTHREADS;
                int row = v >> 3, q = v & 7;
                cpasync16(sB + swzA(row, q)*2, gb + (size_t)row*lb + q*8);
            }
            asm volatile("cp.async.commit_group;");
        };

        uint32_t acc[2][4][2];
#pragma unroll
        for (int mi = 0; mi < 2; mi++)
#pragma unroll
            for (int ni = 0; ni < 4; ni++) { acc[mi][ni][0] = 0u; acc[mi][ni][1] = 0u; }

        issue_chunk(0, 0);
        issue_chunk(1, 1);

        for (int c = 0; c < NC; ++c) {
            if (c + 1 < NC) { asm volatile("cp.async.wait_group 1;" ::: "memory"); }
            else            { asm volatile("cp.async.wait_group 0;" ::: "memory"); }
            __syncthreads();
            uint32_t sA = sbase + (c % 3)*SBUFB;
            uint32_t sB = sA + ABYTES;
#pragma unroll
            for (int ks = 0; ks < 4; ++ks) {
                uint32_t af[2][4], bf[2][4];
                {
                    int cg = ks*2 + a_cgoff;
#pragma unroll
                    for (int mi = 0; mi < 2; mi++)
                        ldsm_x4(af[mi], sA + swzA(a_rbase + mi*16, cg)*2);
                }
                {
                    int krow = ks*16 + b_krow_l;
#pragma unroll
                    for (int j = 0; j < 2; j++)
                        ldsm_x4t(bf[j], sB + swzA(krow, b_cg0 + j*2)*2);
                }
#pragma unroll
                for (int mi = 0; mi < 2; mi++)
#pragma unroll
                    for (int ni = 0; ni < 4; ni++)
                        mma_f16h(acc[mi][ni], af[mi], bf[ni >> 1] + (ni & 1)*2);
            }
            if (c + 2 < NC) issue_chunk(c + 2, (c + 2) % 3);
        }

        // ---------------- fused epilogue ----------------
#pragma unroll
        for (int mi = 0; mi < 2; mi++) {
#pragma unroll
            for (int ni = 0; ni < 4; ni++) {
                int m = m0 + wm*32 + mi*16 + (lane >> 2);
                int n = n0 + wn*32 + ni*8 + 2*(lane & 3);
#pragma unroll
                for (int hh = 0; hh < 2; hh++) {
                    int mm = m + hh*8;
                    float2 v = __half22float2(*(__half2*)&acc[mi][ni][hh]);
                    if (epi == 2) {
                        size_t idx = (size_t)mm*P_ + n;
                        float2 u  = __half22float2(*(const __half2*)(g_U16 + (size_t)t*BP + idx));
                        float2 po = *(const float2*)(g_p + idx);
                        float2 pn, s;
                        pn.x = 0.25f*(v.x + u.x) + 0.75f*po.x; s.x = sigmoidf_(pn.x);
                        pn.y = 0.25f*(v.y + u.y) + 0.75f*po.y; s.y = sigmoidf_(pn.y);
                        *(float2*)(g_p + idx) = pn;
                        *(float2*)(out + (size_t)t*BP + idx) = s;
                        *(__half2*)(ap_out + idx) = __floats2half2_rn(s.x, s.y);
                    } else {
                        size_t idx = (size_t)mm*C_ + n;
                        float2 bc = *(const float2*)(bias_c + n);
                        float2 co = *(const float2*)(g_c + idx);
                        float2 cn, s;
                        cn.x = 0.25f*(v.x + bc.x) + 0.75f*co.x; s.x = sigmoidf_(cn.x);
                        cn.y = 0.25f*(v.y + bc.y) + 0.75f*co.y; s.y = sigmoidf_(cn.y);
                        *(float2*)(g_c + idx) = cn;
                        *(__half2*)(ac_out + idx) = __floats2half2_rn(s.x, s.y);
                    }
                }
            }
        }
    }
}

// =================== U GEMM (f16 acc, TN=128, 2-stage; round-8 measured) ===================
__global__ void __launch_bounds__(NTHREADS, 3) k_gemm_u(
    const float* __restrict__ bias_p)
{
    extern __shared__ __half smem[];
    const int tid = threadIdx.x, lane = tid & 31, wid = tid >> 5;
    const int wm = wid >> 1, wn = wid & 1;
    const int l7 = lane & 7;

    int m0 = blockIdx.x * TM;
    int n0 = blockIdx.y * 128;
    const __half* a0 = g_AH16 + (size_t)m0 * H_;
    const __half* b0 = g_w16_hp + n0;
    const int NC = H_/TKC;                       // 16
    const uint32_t sbase = smem_u32(smem);

    auto issue_chunk = [&](int c, int buf) {
        const __half* ga = a0 + (size_t)c*TKC;
        const __half* gb = b0 + (size_t)c*TKC*P_;
        uint32_t sA = sbase + buf*UBUFB;
        uint32_t sB = sA + ABYTES;
#pragma unroll
        for (int it = 0; it < 4; ++it) {
            int v = tid + it * NTHREADS;
            int row = v >> 3, q = v & 7;
            cpasync16(sA + swzA(row, q)*2, ga + (size_t)row*H_ + q*8);
        }
#pragma unroll
        for (int it = 0; it < 4; ++it) {
            int v = tid + it * NTHREADS;
            int row = v >> 4, q = v & 15;
            cpasync16(sB + swzB(row, q)*2, gb + (size_t)row*P_ + q*8);
        }
        asm volatile("cp.async.commit_group;");
    };

    uint32_t acc[2][8][2];
#pragma unroll
    for (int mi = 0; mi < 2; mi++)
#pragma unroll
        for (int ni = 0; ni < 8; ni++) { acc[mi][ni][0] = 0u; acc[mi][ni][1] = 0u; }

    const int a_rbase = wm*32 + l7 + ((lane >> 3) & 1) * 8;
    const int a_cgoff = (lane >> 4);
    const int b_krow_l = (lane & 15);
    const int b_cg0 = wn*8 + (lane >> 4);

    issue_chunk(0, 0);
    issue_chunk(1, 1);

    for (int c = 0; c < NC; ++c) {
        if (c + 1 < NC) { asm volatile("cp.async.wait_group 1;" ::: "memory"); }
        else            { asm volatile("cp.async.wait_group 0;" ::: "memory"); }
        __syncthreads();
        uint32_t sA = sbase + (c & 1)*UBUFB;
        uint32_t sB = sA + ABYTES;
#pragma unroll
        for (int ks = 0; ks < 4; ++ks) {
            uint32_t af[2][4], bf[4][4];
            {
                int cg = ks*2 + a_cgoff;
#pragma unroll
                for (int mi = 0; mi < 2; mi++)
                    ldsm_x4(af[mi], sA + swzA(a_rbase + mi*16, cg)*2);
            }
            {
                int krow = ks*16 + b_krow_l;
#pragma unroll
                for (int j = 0; j < 4; j++)
                    ldsm_x4t(bf[j], sB + swzB(krow, b_cg0 + j*2)*2);
            }
#pragma unroll
            for (int mi = 0; mi < 2; mi++)
#pragma unroll
                for (int ni = 0; ni < 8; ni++)
                    mma_f16h(acc[mi][ni], af[mi], bf[ni >> 1] + (ni & 1)*2);
        }
        __syncthreads();
        if (c + 2 < NC) issue_chunk(c + 2, c & 1);
    }

#pragma unroll
    for (int mi = 0; mi < 2; mi++) {
#pragma unroll
        for (int ni = 0; ni < 8; ni++) {
            int m = m0 + wm*32 + mi*16 + (lane >> 2);
            int n = n0 + wn*64 + ni*8 + 2*(lane & 3);
            float2 bp = *(const float2*)(bias_p + n);
#pragma unroll
            for (int hh = 0; hh < 2; hh++) {
                float2 v = __half22float2(*(__half2*)&acc[mi][ni][hh]);
                *(__half2*)(g_U16 + (size_t)(m + hh*8)*P_ + n) =
                    __floats2half2_rn(v.x + bp.x, v.y + bp.y);
            }
        }
    }
}

// =================== fp32-acc OH GEMM (proven) ===================
__global__ void __launch_bounds__(NTHREADS, 3) k_gemm_oh(
    const float* __restrict__ bias_h)
{
    extern __shared__ __half smem[];
    const int tid = threadIdx.x, lane = tid & 31, wid = tid >> 5;
    const int wm = wid >> 1, wn = wid & 1;
    const int l7 = lane & 7;

    int m0 = blockIdx.x * TM;
    int n0 = blockIdx.y * OTN;
    const __half* a0 = g_in16 + (size_t)m0 * O_;
    const __half* b0 = g_w16_oh + n0;
    const int NC = O_/TKC;                       // 8
    const uint32_t sbase = smem_u32(smem);

    auto issue_chunk = [&](int c, int buf) {
        const __half* ga = a0 + (size_t)c*TKC;
        const __half* gb = b0 + (size_t)c*TKC*H_;
        uint32_t sA = sbase + buf*OBUFBYTES;
        uint32_t sB = sA + ABYTES;
#pragma unroll
        for (int it = 0; it < 4; ++it) {
            int v = tid + it * NTHREADS;
            int row = v >> 3, q = v & 7;
            cpasync16(sA + swzA(row, q)*2, ga + (size_t)row*O_ + q*8);
        }
#pragma unroll
        for (int it = 0; it < 2; ++it) {
            int v = tid + it * NTHREADS;
            int row = v >> 3, q = v & 7;
            cpasync16(sB + swzA(row, q)*2, gb + (size_t)row*H_ + q*8);
        }
        asm volatile("cp.async.commit_group;");
    };

    float acc[2][4][4];
#pragma unroll
    for (int mi = 0; mi < 2; mi++)
#pragma unroll
        for (int ni = 0; ni < 4; ni++)
#pragma unroll
            for (int q = 0; q < 4; q++) acc[mi][ni][q] = 0.0f;

    const int a_rbase = wm*32 + l7 + ((lane >> 3) & 1) * 8;
    const int a_cgoff = (lane >> 4);
    const int b_krow_l = (lane & 15);
    const int b_cg0 = wn*4 + (lane >> 4);

    issue_chunk(0, 0);
    issue_chunk(1, 1);

    for (int c = 0; c < NC; ++c) {
        if (c + 1 < NC) { asm volatile("cp.async.wait_group 1;" ::: "memory"); }
        else            { asm volatile("cp.async.wait_group 0;" ::: "memory"); }
        __syncthreads();
        uint32_t sA = sbase + (c % 3)*OBUFBYTES;
        uint32_t sB = sA + ABYTES;
#pragma unroll
        for (int ks = 0; ks < 4; ++ks) {
            uint32_t af[2][4], bf[2][4];
            {
                int cg = ks*2 + a_cgoff;
#pragma unroll
                for (int mi = 0; mi < 2; mi++)
                    ldsm_x4(af[mi], sA + swzA(a_rbase + mi*16, cg)*2);
            }
            {
                int krow = ks*16 + b_krow_l;
#pragma unroll
                for (int j = 0; j < 2; j++)
                    ldsm_x4t(bf[j], sB + swzA(krow, b_cg0 + j*2)*2);
            }
#pragma unroll
            for (int mi = 0; mi < 2; mi++)
#pragma unroll
                for (int ni = 0; ni < 4; ni++)
                    mma_f16f32(acc[mi][ni], af[mi], bf[ni >> 1] + (ni & 1)*2);
        }
        if (c + 2 < NC) issue_chunk(c + 2, (c + 2) % 3);
    }

#pragma unroll
    for (int mi = 0; mi < 2; mi++) {
#pragma unroll
        for (int ni = 0; ni < 4; ni++) {
            int m = m0 + wm*32 + mi*16 + (lane >> 2);
            int n = n0 + wn*32 + ni*8 + 2*(lane & 3);
#pragma unroll
            for (int half = 0; half < 2; half++) {
                int mm = m + half*8;
                float v0 = acc[mi][ni][2*half], v1 = acc[mi][ni][2*half+1];
                float2 bh = *(const float2*)(bias_h + n);
                float p0 = v0 + bh.x, p1 = v1 + bh.y;
                size_t idx = (size_t)mm*H_ + n;
#pragma unroll
                for (int tt = 0; tt < T_; tt++) {
                    float sc = c_sc[tt];
                    *(__half2*)(g_AH16 + (size_t)tt*BH + idx) =
                        __floats2half2_rn(sigmoidf_(p0*sc), sigmoidf_(p1*sc));
                }
            }
        }
    }
}

// ---------------- prep: coalesced fp16 convert ----------------
__global__ void k_conv(const float* __restrict__ inputs,
                       const float* __restrict__ w_oh, const float* __restrict__ w_hp,
                       const float* __restrict__ w_pp, const float* __restrict__ w_pc,
                       const float* __restrict__ w_cp) {
    int i4 = blockIdx.x * blockDim.x + threadIdx.x;
    const int S0 = B_*O_, S1 = S0 + O_*H_, S2 = S1 + H_*P_, S3 = S2 + P_*P_,
              S4 = S3 + P_*C_, S5 = S4 + C_*P_;
    int j = i4 * 4;
    if (j >= S5) return;
    const float* src; __half* dst; int rel; bool diag = false;
    if (j < S0)      { src = inputs; dst = g_in16;  rel = j; }
    else if (j < S1) { src = w_oh;   dst = g_w16_oh; rel = j - S0; }
    else if (j < S2) { src = w_hp;   dst = g_w16_hp; rel = j - S1; }
    else if (j < S3) { src = w_pp;   dst = g_w16_pp; rel = j - S2; diag = true; }
    else if (j < S4) { src = w_pc;   dst = g_w16_pc; rel = j - S3; }
    else             { src = w_cp;   dst = g_w16_cp; rel = j - S4; }
    float4 v = *(const float4*)(src + rel);
    if (diag) {
        int k = rel >> 10, nb = rel & 1023;
        if (k == nb)     v.x = 0.0f;
        if (k == nb + 1) v.y = 0.0f;
        if (k == nb + 2) v.z = 0.0f;
        if (k == nb + 3) v.w = 0.0f;
    }
    __half2 h01 = __floats2half2_rn(v.x, v.y);
    __half2 h23 = __floats2half2_rn(v.z, v.w);
    uint2 o;
    o.x = *(uint32_t*)&h01;
    o.y = *(uint32_t*)&h23;
    *(uint2*)(dst + rel) = o;
}

// ---------------- column-sum partials ----------------
__global__ void k_colsum(const float* __restrict__ w_pp, const float* __restrict__ w_cp,
                         const float* __restrict__ w_pc) {
    int n = blockIdx.x * 256 + threadIdx.x;
    int seg = blockIdx.y;
    int mat = blockIdx.z;
    if (mat == 0) {
        int k0 = seg * 128;
        float s = 0.0f;
        for (int k = k0; k < k0 + 128; k++)
            if (k != n) s += w_pp[(size_t)k*P_ + n];
        g_csp_pp0[seg*P_ + n] = s;
    } else if (mat == 1) {
        int k0 = seg * 64;
        float s = 0.0f;
        for (int k = k0; k < k0 + 64; k++)
            s += w_cp[(size_t)k*P_ + n];
        g_csp_cp[seg*P_ + n] = s;
    } else {
        if (n >= C_) return;
        int k0 = seg * 128;
        float s = 0.0f;
        for (int k = k0; k < k0 + 128; k++)
            s += w_pc[(size_t)k*C_ + n];
        g_csp_pc[seg*C_ + n] = s;
    }
}

// ---------------- step 0 (also resets the grid-barrier counter) ----------------
__global__ void k_step0(const float* __restrict__ bias_c, float* __restrict__ out) {
    int i = blockIdx.x * blockDim.x + threadIdx.x;
    if (i == 0) g_barv = 0u;                 // reset persistent-kernel barrier each replay
    if (i < BP) {
        int n = i & (P_ - 1);
        float cs = 0.0f;
#pragma unroll
        for (int s = 0; s < 8; s++) cs += g_csp_pp0[s*P_ + n] + g_csp_cp[s*P_ + n];
        float pn = 0.25f * (__half2float(g_U16[i]) + 0.5f * cs);
        g_p[i] = pn;
        float sg = sigmoidf_(pn);
        out[i] = sg;
        g_ap16A[i] = __float2half(sg);
    } else if (i < BP + BC) {
        int j = i - BP;
        int n = j & (C_ - 1);
        float cs = 0.0f;
#pragma unroll
        for (int s = 0; s < 8; s++) cs += g_csp_pc[s*C_ + n];
        float cn = 0.25f * (0.5f * cs + bias_c[n]);
        g_c[j] = cn;
        g_ac16A[j] = __float2half(sigmoidf_(cn));
    }
}

// ---------------- entry point ----------------
extern "C" void kernel_launch(void* const* d_in, const int* in_sizes, int n_in,
                              void* d_out, int out_size) {
    const float* inputs = (const float*)d_in[0];
    const float* w_oh   = (const float*)d_in[1];
    const float* w_hp   = (const float*)d_in[2];
    const float* w_pp   = (const float*)d_in[3];
    const float* w_pc   = (const float*)d_in[4];
    const float* w_cp   = (const float*)d_in[5];
    const float* bias_h = (const float*)d_in[6];
    const float* bias_p = (const float*)d_in[7];
    const float* bias_c = (const float*)d_in[8];
    float* out = (float*)d_out;

    cudaFuncSetAttribute(k_gemm_u,  cudaFuncAttributeMaxDynamicSharedMemorySize, SMEM_U);
    cudaFuncSetAttribute(k_steps,   cudaFuncAttributeMaxDynamicSharedMemorySize, SMEM_STEP);
    cudaFuncSetAttribute(k_gemm_oh, cudaFuncAttributeMaxDynamicSharedMemorySize, SMEM32);

    const int TOT4 = (B_*O_ + O_*H_ + H_*P_ + P_*P_ + P_*C_ + C_*P_) / 4;
    k_conv<<<(TOT4 + 255)/256, 256>>>(inputs, w_oh, w_hp, w_pp, w_pc, w_cp);
    k_colsum<<<dim3(4, 8, 3), 256>>>(w_pp, w_cp, w_pc);

    // OH GEMM (fp32 acc): writes g_AH16 for all 12 timesteps
    k_gemm_oh<<<dim3(B_/TM, H_/OTN), NTHREADS, SMEM32>>>(bias_h);

    // U[t] = ah_t @ w_hp + bias_p  (f16 acc, TN=128)
    k_gemm_u<<<dim3(T_*B_/TM, P_/128), NTHREADS, SMEM_U>>>(bias_p);

    // step 0 (also resets grid barrier)
    k_step0<<<(BP + BC + 255)/256, 256>>>(bias_c, out);

    // steps 1..11: ONE persistent kernel, grid barrier between steps
    k_steps<<<NCTA_STEP, NTHREADS, SMEM_STEP>>>(bias_c, out);
}